// round 3
// baseline (speedup 1.0000x reference)
#include <cuda_runtime.h>
#include <cuda_bf16.h>
#include <math.h>
#include <stdint.h>

// ---------------- problem constants ----------------
#define BB      8
#define TT      4096
#define DD      512
#define QQ      4
#define KK_CB   1024
#define KER     5
#define TOUT    2048
#define NTOK    32768
#define NELEM   (NTOK * DD)              // 16777216
#define Y_SZ    (BB * TOUT * DD)         // 8388608
#define QO_SZ   NELEM
#define IDX_SZ  (QQ * NTOK)
#define LOSS_OFF (Y_SZ + QO_SZ + IDX_SZ)
#define KCONV   (KER * DD)               // 2560

// smem tile geometry: 128 rows x 32 bf16, padded row stride 40 elems (80 B)
#define PADE    40
#define TILE_B  10240
#define BUF_B   (4 * TILE_B)             // A_hi, A_lo, B_hi, B_lo
#define SMEM_DYN (2 * BUF_B)             // 81920

// ---------------- persistent scratch ----------------
__device__ float  g_residual[NELEM];
__device__ __nv_bfloat16 g_a_hi[NELEM], g_a_lo[NELEM];
__device__ __nv_bfloat16 g_q_hi[NELEM], g_q_lo[NELEM];
__device__ __nv_bfloat16 g_cb_hi[QQ*KK_CB*DD], g_cb_lo[QQ*KK_CB*DD];
__device__ __nv_bfloat16 g_wt_hi[DD*KCONV], g_wt_lo[DD*KCONV];
__device__ float  g_cnorm[QQ * KK_CB];
__device__ int    g_idx[QQ * NTOK];
__device__ float  g_d1[NTOK], g_d2[NTOK];
__device__ double g_loss;

// ---------------- PTX helpers (sm_80-compatible) ----------------
__device__ __forceinline__ uint32_t smem_u32(const void* p) {
    uint32_t a;
    asm("{ .reg .u64 t; cvta.to.shared.u64 t, %1; cvt.u32.u64 %0, t; }" : "=r"(a) : "l"(p));
    return a;
}
__device__ __forceinline__ void cp16(uint32_t s, const void* g) {
    asm volatile("cp.async.cg.shared.global [%0], [%1], 16;" :: "r"(s), "l"(g));
}
__device__ __forceinline__ void cp16z(uint32_t s, const void* g, int valid) {
    int n = valid ? 16 : 0;
    asm volatile("cp.async.cg.shared.global [%0], [%1], 16, %2;" :: "r"(s), "l"(g), "r"(n));
}
#define CP_COMMIT() asm volatile("cp.async.commit_group;" ::: "memory")
#define CP_WAIT1()  asm volatile("cp.async.wait_group 1;" ::: "memory")
#define CP_WAIT0()  asm volatile("cp.async.wait_group 0;" ::: "memory")

__device__ __forceinline__ void ldsm4(uint32_t* r, uint32_t a) {
    asm volatile("ldmatrix.sync.aligned.m8n8.x4.shared.b16 {%0,%1,%2,%3}, [%4];"
                 : "=r"(r[0]), "=r"(r[1]), "=r"(r[2]), "=r"(r[3]) : "r"(a));
}
__device__ __forceinline__ void mma_bf16(float* c, const uint32_t* a, uint32_t b0, uint32_t b1) {
    asm volatile("mma.sync.aligned.m16n8k16.row.col.f32.bf16.bf16.f32 "
                 "{%0,%1,%2,%3},{%4,%5,%6,%7},{%8,%9},{%0,%1,%2,%3};"
                 : "+f"(c[0]), "+f"(c[1]), "+f"(c[2]), "+f"(c[3])
                 : "r"(a[0]), "r"(a[1]), "r"(a[2]), "r"(a[3]), "r"(b0), "r"(b1));
}

__device__ __forceinline__ void split1(float v, __nv_bfloat16& h, __nv_bfloat16& l) {
    h = __float2bfloat16(v);
    l = __float2bfloat16(v - __bfloat162float(h));
}
__device__ __forceinline__ void upd2(float d, int k, float& d1, float& d2, int& k1) {
    if (d < d1) { d2 = d1; d1 = d; k1 = k; }
    else if (d < d2) { d2 = d; }
}

// ---------------- prep kernels ----------------
__global__ void cnorm_kernel(const float* __restrict__ cb) {
    if (blockIdx.x == 0 && threadIdx.x == 0) g_loss = 0.0;
    int w = (blockIdx.x * blockDim.x + threadIdx.x) >> 5;
    int lane = threadIdx.x & 31;
    if (w >= QQ * KK_CB) return;
    const float* c = cb + (size_t)w * DD;
    float s = 0.f;
    #pragma unroll
    for (int d = lane; d < DD; d += 32) { float v = c[d]; s += v * v; }
    #pragma unroll
    for (int o = 16; o > 0; o >>= 1) s += __shfl_down_sync(0xffffffffu, s, o);
    if (lane == 0) g_cnorm[w] = s;
}
__global__ void split_x_kernel(const float* __restrict__ x) {
    for (int e = blockIdx.x * blockDim.x + threadIdx.x; e < NELEM; e += gridDim.x * blockDim.x)
        split1(x[e], g_a_hi[e], g_a_lo[e]);
}
__global__ void split_cb_kernel(const float* __restrict__ cb) {
    int n = QQ * KK_CB * DD;
    for (int e = blockIdx.x * blockDim.x + threadIdx.x; e < n; e += gridDim.x * blockDim.x)
        split1(cb[e], g_cb_hi[e], g_cb_lo[e]);
}
__global__ void transpose_w_kernel(const float* __restrict__ w) {
    int n = KER * DD * DD;
    for (int e = blockIdx.x * blockDim.x + threadIdx.x; e < n; e += gridDim.x * blockDim.x) {
        int kk = e / (DD * DD);
        int r  = e - kk * DD * DD;
        int cin = r >> 9, cout = r & 511;
        int o = cout * KCONV + kk * DD + cin;
        split1(w[e], g_wt_hi[o], g_wt_lo[o]);
    }
}

// ---------------- VQ argmin via mma.sync (bf16 hi/lo x3) ----------------
__global__ __launch_bounds__(256, 1)
void vq_argmin_mma(int stage) {
    extern __shared__ char smem[];
    uint32_t sb = smem_u32(smem);
    int tid = threadIdx.x, lane = tid & 31, w = tid >> 5;
    int warp_m = w & 3, warp_n = w >> 2;
    int row0 = blockIdx.x * 128;

    const __nv_bfloat16* __restrict__ cbh = g_cb_hi + (size_t)stage * KK_CB * DD;
    const __nv_bfloat16* __restrict__ cbl = g_cb_lo + (size_t)stage * KK_CB * DD;
    const float* __restrict__ cn = g_cnorm + stage * KK_CB;

    float acc[2][8][4];
    #pragma unroll
    for (int m = 0; m < 2; m++)
        #pragma unroll
        for (int n = 0; n < 8; n++)
            #pragma unroll
            for (int q = 0; q < 4; q++) acc[m][n][q] = 0.f;

    float d1r[4], d2r[4]; int k1r[4];
    #pragma unroll
    for (int s = 0; s < 4; s++) { d1r[s] = 3.4e38f; d2r[s] = 3.4e38f; k1r[s] = 0; }

    // ldmatrix per-lane address component (within a 16-row x 32-col k-chunk tile)
    // row = base + (lane&15), col = ks*16 + ((lane>>4)&1)*8
    // byte off = row*80 + col*2

    // --- prologue: chunk 0 ---
    {
        int nt = 0, kc = 0;
        uint32_t base = sb;
        #pragma unroll
        for (int i = 0; i < 2; i++) {
            int s = tid + i * 256;
            int r = s >> 2, c = s & 3;
            uint32_t so = r * 80 + c * 16;
            size_t ga = (size_t)(row0 + r) * DD + kc * 32 + c * 8;
            size_t gb = (size_t)(nt * 128 + r) * DD + kc * 32 + c * 8;
            cp16(base + so,              g_a_hi + ga);
            cp16(base + TILE_B + so,     g_a_lo + ga);
            cp16(base + 2 * TILE_B + so, cbh + gb);
            cp16(base + 3 * TILE_B + so, cbl + gb);
        }
        CP_COMMIT();
    }

    for (int it = 0; it < 128; ++it) {
        if (it < 127) {
            int nit = it + 1;
            int nt = nit >> 4, kc = nit & 15;
            uint32_t base = sb + (nit & 1) * BUF_B;
            #pragma unroll
            for (int i = 0; i < 2; i++) {
                int s = tid + i * 256;
                int r = s >> 2, c = s & 3;
                uint32_t so = r * 80 + c * 16;
                size_t ga = (size_t)(row0 + r) * DD + kc * 32 + c * 8;
                size_t gb = (size_t)(nt * 128 + r) * DD + kc * 32 + c * 8;
                cp16(base + so,              g_a_hi + ga);
                cp16(base + TILE_B + so,     g_a_lo + ga);
                cp16(base + 2 * TILE_B + so, cbh + gb);
                cp16(base + 3 * TILE_B + so, cbl + gb);
            }
            CP_COMMIT();
            CP_WAIT1();
        } else {
            CP_WAIT0();
        }
        __syncthreads();

        uint32_t base = sb + (it & 1) * BUF_B;
        #pragma unroll
        for (int ks = 0; ks < 2; ++ks) {
            uint32_t lcomp = (uint32_t)((lane & 15) * 80 + (ks * 16 + ((lane >> 4) & 1) * 8) * 2);
            uint32_t ah[2][4], al[2][4];
            #pragma unroll
            for (int mf = 0; mf < 2; mf++) {
                uint32_t off = (uint32_t)((warp_m * 32 + mf * 16) * 80) + lcomp;
                ldsm4(ah[mf], base + off);
                ldsm4(al[mf], base + TILE_B + off);
            }
            uint32_t bh[4][4], bl[4][4];
            #pragma unroll
            for (int np = 0; np < 4; np++) {
                uint32_t off = (uint32_t)((warp_n * 64 + np * 16) * 80) + lcomp;
                ldsm4(bh[np], base + 2 * TILE_B + off);
                ldsm4(bl[np], base + 3 * TILE_B + off);
            }
            #pragma unroll
            for (int mf = 0; mf < 2; mf++)
                #pragma unroll
                for (int nf = 0; nf < 8; nf++) {
                    int np = nf >> 1, od = nf & 1;
                    mma_bf16(acc[mf][nf], ah[mf], bh[np][od], bh[np][od + 2]);
                    mma_bf16(acc[mf][nf], ah[mf], bl[np][od], bl[np][od + 2]);
                    mma_bf16(acc[mf][nf], al[mf], bh[np][od], bh[np][od + 2]);
                }
        }

        if ((it & 15) == 15) {
            int nt = it >> 4;
            #pragma unroll
            for (int mf = 0; mf < 2; mf++)
                #pragma unroll
                for (int nf = 0; nf < 8; nf++) {
                    int c0 = nt * 128 + warp_n * 64 + nf * 8 + 2 * (lane & 3);
                    float n0 = __ldg(cn + c0), n1 = __ldg(cn + c0 + 1);
                    upd2(n0 - 2.f * acc[mf][nf][0], c0,     d1r[mf*2],   d2r[mf*2],   k1r[mf*2]);
                    upd2(n1 - 2.f * acc[mf][nf][1], c0 + 1, d1r[mf*2],   d2r[mf*2],   k1r[mf*2]);
                    upd2(n0 - 2.f * acc[mf][nf][2], c0,     d1r[mf*2+1], d2r[mf*2+1], k1r[mf*2+1]);
                    upd2(n1 - 2.f * acc[mf][nf][3], c0 + 1, d1r[mf*2+1], d2r[mf*2+1], k1r[mf*2+1]);
                    #pragma unroll
                    for (int q = 0; q < 4; q++) acc[mf][nf][q] = 0.f;
                }
        }
        __syncthreads();
    }

    // cross-warp top-2 merge (reuse smem)
    float* sd1 = (float*)smem;
    float* sd2 = (float*)(smem + 4096);
    int*   sk1 = (int*)(smem + 8192);
    #pragma unroll
    for (int slot = 0; slot < 4; ++slot) {
        int mf = slot >> 1, hf = slot & 1;
        int row = warp_m * 32 + mf * 16 + hf * 8 + (lane >> 2);
        int c8 = warp_n * 4 + (lane & 3);
        sd1[row * 8 + c8] = d1r[slot];
        sd2[row * 8 + c8] = d2r[slot];
        sk1[row * 8 + c8] = k1r[slot];
    }
    __syncthreads();
    if (tid < 128) {
        float bd1 = 3.4e38f, bd2 = 3.4e38f; int bk = 0;
        #pragma unroll
        for (int j = 0; j < 8; j++) {
            float a1 = sd1[tid * 8 + j], a2 = sd2[tid * 8 + j];
            int ak = sk1[tid * 8 + j];
            if (a1 < bd1 || (a1 == bd1 && ak < bk)) {
                bd2 = fminf(bd1, a2); bd1 = a1; bk = ak;
            } else {
                bd2 = fminf(bd2, a1);
            }
        }
        int tok = row0 + tid;
        g_idx[stage * NTOK + tok] = bk;
        g_d1[tok] = bd1;
        g_d2[tok] = bd2;
    }
}

// ---------------- exact-fp32 fixup for near-tie tokens ----------------
__global__ void vq_fixup(const float* __restrict__ x, const float* __restrict__ cb, int stage) {
    int wg = (blockIdx.x * blockDim.x + threadIdx.x) >> 5;
    if (wg >= NTOK) return;
    int lane = threadIdx.x & 31;
    float gap = g_d2[wg] - g_d1[wg];
    if (gap > 0.05f) return;

    const float* r = (stage == 0) ? (x + (size_t)wg * DD) : (g_residual + (size_t)wg * DD);
    float rv[16];
    #pragma unroll
    for (int i = 0; i < 16; ++i) rv[i] = r[lane + 32 * i];
    const float* cbs = cb + (size_t)stage * KK_CB * DD;
    const float* cn = g_cnorm + stage * KK_CB;

    float bd = 3.4e38f; int bk = 0;
    for (int k = 0; k < KK_CB; ++k) {
        const float* c = cbs + (size_t)k * DD;
        float s = 0.f;
        #pragma unroll
        for (int i = 0; i < 16; ++i) s += rv[i] * c[lane + 32 * i];
        #pragma unroll
        for (int o = 16; o > 0; o >>= 1) s += __shfl_xor_sync(0xffffffffu, s, o);
        float d = cn[k] - 2.0f * s;
        if (d < bd) { bd = d; bk = k; }
    }
    if (lane == 0) g_idx[stage * NTOK + wg] = bk;
}

// ---------------- residual update: fp32 + bf16 splits + loss ----------------
__global__ void vq_update_kernel(const float* __restrict__ x,
                                 const float* __restrict__ cb_stage,
                                 int stage) {
    __shared__ float sred[256];
    const float4* src = (const float4*)((stage == 0) ? x : g_residual);
    float4* res = (float4*)g_residual;
    const float4* cb4 = (const float4*)cb_stage;
    const int* idx = g_idx + stage * NTOK;

    float lsum = 0.f;
    int n4 = NELEM / 4;
    for (int e = blockIdx.x * blockDim.x + threadIdx.x; e < n4; e += gridDim.x * blockDim.x) {
        int tok = e >> 7;
        int d4  = e & 127;
        int k   = __ldg(idx + tok);
        float4 r = src[e];
        float4 q = cb4[(size_t)k * 128 + d4];
        float nx = r.x - q.x, ny = r.y - q.y, nz = r.z - q.z, nw = r.w - q.w;
        lsum += nx * nx + ny * ny + nz * nz + nw * nw;
        res[e] = make_float4(nx, ny, nz, nw);
        if (stage < QQ - 1) {
            int b = e * 4;
            split1(nx, g_a_hi[b+0], g_a_lo[b+0]);
            split1(ny, g_a_hi[b+1], g_a_lo[b+1]);
            split1(nz, g_a_hi[b+2], g_a_lo[b+2]);
            split1(nw, g_a_hi[b+3], g_a_lo[b+3]);
        }
    }
    sred[threadIdx.x] = lsum;
    __syncthreads();
    for (int o = 128; o > 0; o >>= 1) {
        if (threadIdx.x < o) sred[threadIdx.x] += sred[threadIdx.x + o];
        __syncthreads();
    }
    if (threadIdx.x == 0) atomicAdd(&g_loss, (double)sred[0]);
}

// ---------------- quantized_out = x - residual ; emit splits ----------------
__global__ void finish_quant_kernel(const float* __restrict__ x, float* __restrict__ quant) {
    int n4 = NELEM / 4;
    const float4* x4 = (const float4*)x;
    const float4* r4 = (const float4*)g_residual;
    float4* q4 = (float4*)quant;
    for (int e = blockIdx.x * blockDim.x + threadIdx.x; e < n4; e += gridDim.x * blockDim.x) {
        float4 a = x4[e], b = r4[e];
        float4 q = make_float4(a.x - b.x, a.y - b.y, a.z - b.z, a.w - b.w);
        q4[e] = q;
        int i = e * 4;
        split1(q.x, g_q_hi[i+0], g_q_lo[i+0]);
        split1(q.y, g_q_hi[i+1], g_q_lo[i+1]);
        split1(q.z, g_q_hi[i+2], g_q_lo[i+2]);
        split1(q.w, g_q_hi[i+3], g_q_lo[i+3]);
    }
}

// ---------------- conv1d (stride2, SAME) + GELU via mma.sync ----------------
__global__ __launch_bounds__(256, 1)
void conv_gelu_mma(float* __restrict__ y) {
    extern __shared__ char smem[];
    uint32_t sb = smem_u32(smem);
    int tid = threadIdx.x, lane = tid & 31, w = tid >> 5;
    int warp_m = w & 3, warp_n = w >> 2;
    int row0 = blockIdx.x * 128;
    int col0 = blockIdx.y * 128;

    float acc[2][8][4];
    #pragma unroll
    for (int m = 0; m < 2; m++)
        #pragma unroll
        for (int n = 0; n < 8; n++)
            #pragma unroll
            for (int q = 0; q < 4; q++) acc[m][n][q] = 0.f;

    // --- prologue: chunk 0 ---
    {
        int kk = 0, cin0 = 0;
        uint32_t base = sb;
        #pragma unroll
        for (int i = 0; i < 2; i++) {
            int s = tid + i * 256;
            int r = s >> 2, c = s & 3;
            uint32_t so = r * 80 + c * 16;
            int orow = row0 + r;
            int bb = orow >> 11, to = orow & 2047;
            int tin = 2 * to + kk - 1;
            int valid = ((unsigned)tin < (unsigned)TT);
            int tcl = valid ? tin : 0;
            size_t ga = ((size_t)bb * TT + tcl) * DD + cin0 + c * 8;
            cp16z(base + so,              g_q_hi + ga, valid);
            cp16z(base + TILE_B + so,     g_q_lo + ga, valid);
            size_t gb = (size_t)(col0 + r) * KCONV + kk * DD + cin0 + c * 8;
            cp16(base + 2 * TILE_B + so,  g_wt_hi + gb);
            cp16(base + 3 * TILE_B + so,  g_wt_lo + gb);
        }
        CP_COMMIT();
    }

    for (int it = 0; it < 80; ++it) {
        if (it < 79) {
            int nit = it + 1;
            int kk = nit >> 4, cin0 = (nit & 15) * 32;
            uint32_t base = sb + (nit & 1) * BUF_B;
            #pragma unroll
            for (int i = 0; i < 2; i++) {
                int s = tid + i * 256;
                int r = s >> 2, c = s & 3;
                uint32_t so = r * 80 + c * 16;
                int orow = row0 + r;
                int bb = orow >> 11, to = orow & 2047;
                int tin = 2 * to + kk - 1;
                int valid = ((unsigned)tin < (unsigned)TT);
                int tcl = valid ? tin : 0;
                size_t ga = ((size_t)bb * TT + tcl) * DD + cin0 + c * 8;
                cp16z(base + so,              g_q_hi + ga, valid);
                cp16z(base + TILE_B + so,     g_q_lo + ga, valid);
                size_t gb = (size_t)(col0 + r) * KCONV + kk * DD + cin0 + c * 8;
                cp16(base + 2 * TILE_B + so,  g_wt_hi + gb);
                cp16(base + 3 * TILE_B + so,  g_wt_lo + gb);
            }
            CP_COMMIT();
            CP_WAIT1();
        } else {
            CP_WAIT0();
        }
        __syncthreads();

        uint32_t base = sb + (it & 1) * BUF_B;
        #pragma unroll
        for (int ks = 0; ks < 2; ++ks) {
            uint32_t lcomp = (uint32_t)((lane & 15) * 80 + (ks * 16 + ((lane >> 4) & 1) * 8) * 2);
            uint32_t ah[2][4], al[2][4];
            #pragma unroll
            for (int mf = 0; mf < 2; mf++) {
                uint32_t off = (uint32_t)((warp_m * 32 + mf * 16) * 80) + lcomp;
                ldsm4(ah[mf], base + off);
                ldsm4(al[mf], base + TILE_B + off);
            }
            uint32_t bh[4][4], bl[4][4];
            #pragma unroll
            for (int np = 0; np < 4; np++) {
                uint32_t off = (uint32_t)((warp_n * 64 + np * 16) * 80) + lcomp;
                ldsm4(bh[np], base + 2 * TILE_B + off);
                ldsm4(bl[np], base + 3 * TILE_B + off);
            }
            #pragma unroll
            for (int mf = 0; mf < 2; mf++)
                #pragma unroll
                for (int nf = 0; nf < 8; nf++) {
                    int np = nf >> 1, od = nf & 1;
                    mma_bf16(acc[mf][nf], ah[mf], bh[np][od], bh[np][od + 2]);
                    mma_bf16(acc[mf][nf], ah[mf], bl[np][od], bl[np][od + 2]);
                    mma_bf16(acc[mf][nf], al[mf], bh[np][od], bh[np][od + 2]);
                }
        }
        __syncthreads();
    }

    // epilogue: GELU + store
    #pragma unroll
    for (int mf = 0; mf < 2; mf++) {
        int rbase = row0 + warp_m * 32 + mf * 16 + (lane >> 2);
        #pragma unroll
        for (int nf = 0; nf < 8; nf++) {
            int c0 = col0 + warp_n * 64 + nf * 8 + 2 * (lane & 3);
            #pragma unroll
            for (int q = 0; q < 4; q++) {
                int row = rbase + (q >> 1) * 8;
                int col = c0 + (q & 1);
                float v = acc[mf][nf][q];
                float g = 0.5f * v * (1.0f + erff(v * 0.70710678118654752f));
                y[(size_t)row * DD + col] = g;
            }
        }
    }
}

// ---------------- indices (as float) + loss ----------------
__global__ void finalize_kernel(float* __restrict__ out) {
    int i = blockIdx.x * blockDim.x + threadIdx.x;
    if (i < IDX_SZ) out[Y_SZ + QO_SZ + i] = (float)g_idx[i];
    if (i == 0)     out[LOSS_OFF] = (float)(0.25 * g_loss / (double)NELEM);
}

// ---------------- launch ----------------
extern "C" void kernel_launch(void* const* d_in, const int* in_sizes, int n_in,
                              void* d_out, int out_size) {
    const float* x  = (const float*)d_in[0];
    const float* cb = (const float*)d_in[1];
    const float* w  = (const float*)d_in[2];
    float* out   = (float*)d_out;
    float* y     = out;
    float* quant = out + Y_SZ;

    cudaFuncSetAttribute(vq_argmin_mma, cudaFuncAttributeMaxDynamicSharedMemorySize, SMEM_DYN);
    cudaFuncSetAttribute(conv_gelu_mma, cudaFuncAttributeMaxDynamicSharedMemorySize, SMEM_DYN);

    cnorm_kernel<<<(QQ * KK_CB * 32 + 255) / 256, 256>>>(cb);
    split_x_kernel<<<2048, 256>>>(x);
    split_cb_kernel<<<2048, 256>>>(cb);
    transpose_w_kernel<<<2048, 256>>>(w);

    for (int s = 0; s < QQ; ++s) {
        vq_argmin_mma<<<NTOK / 128, 256, SMEM_DYN>>>(s);
        vq_fixup<<<NTOK / 8, 256>>>(x, cb, s);
        vq_update_kernel<<<2048, 256>>>(x, cb + (size_t)s * KK_CB * DD, s);
    }
    finish_quant_kernel<<<4096, 256>>>(x, quant);
    conv_gelu_mma<<<dim3(BB * TOUT / 128, DD / 128), 256, SMEM_DYN>>>(y);
    finalize_kernel<<<(IDX_SZ + 255) / 256, 256>>>(out);
}

// round 4
// speedup vs baseline: 2.0941x; 2.0941x over previous
#include <cuda_runtime.h>
#include <math.h>
#include <stdint.h>

// ---------------- problem constants ----------------
#define BB      8
#define TT      4096
#define DD      512
#define QQ      4
#define KK_CB   1024
#define KER     5
#define TOUT    2048
#define NTOK    32768
#define NELEM   (NTOK * DD)              // 16777216
#define Y_SZ    (BB * TOUT * DD)         // 8388608
#define QO_SZ   NELEM
#define IDX_SZ  (QQ * NTOK)
#define LOSS_OFF (Y_SZ + QO_SZ + IDX_SZ)

// ---------------- persistent scratch ----------------
__device__ float  g_residual[NELEM];     // 64 MB
__device__ float  g_cnorm[QQ * KK_CB];
__device__ int    g_idx[QQ * NTOK];
__device__ double g_loss;

// ---------------- packed fp32x2 helpers (Blackwell FFMA2) ----------------
__device__ __forceinline__ unsigned long long pack2(float a) {
    unsigned long long r;
    asm("mov.b64 %0, {%1, %1};" : "=l"(r) : "f"(a));
    return r;
}
__device__ __forceinline__ void fma2(unsigned long long& acc, unsigned long long a, unsigned long long b) {
    asm("fma.rn.f32x2 %0, %1, %2, %0;" : "+l"(acc) : "l"(a), "l"(b));
}
__device__ __forceinline__ float2 unpack2(unsigned long long v) {
    float2 f;
    asm("mov.b64 {%0, %1}, %2;" : "=f"(f.x), "=f"(f.y) : "l"(v));
    return f;
}

// ---------------- codebook norms (+loss reset) ----------------
__global__ void cnorm_kernel(const float* __restrict__ cb) {
    if (blockIdx.x == 0 && threadIdx.x == 0) g_loss = 0.0;
    int w    = (blockIdx.x * blockDim.x + threadIdx.x) >> 5;
    int lane = threadIdx.x & 31;
    if (w >= QQ * KK_CB) return;
    const float* c = cb + (size_t)w * DD;
    float s = 0.f;
    #pragma unroll
    for (int d = lane; d < DD; d += 32) { float v = c[d]; s += v * v; }
    #pragma unroll
    for (int o = 16; o > 0; o >>= 1) s += __shfl_down_sync(0xffffffffu, s, o);
    if (lane == 0) g_cnorm[w] = s;
}

// ---------------- fused VQ stage: distance GEMM + argmin + residual update + loss ----------------
// dist(token,k) = ||c_k||^2 - 2 * r . c_k
// Tile: 128 tokens x 128 codes, K-step 16, 8x8 microtile via f32x2, 256 threads.
// Epilogue: residual[tok] -= cb[best]; loss += ||q - r||^2; stage 3 also emits quantized_out.
__global__ __launch_bounds__(256)
void vq_stage_kernel(const float* __restrict__ x,
                     const float* __restrict__ cb_stage,   // [1024,512] fp32
                     float* __restrict__ quant,            // written only when stage==QQ-1
                     int stage) {
    __shared__ __align__(16) float As[16][132];
    __shared__ __align__(16) float Bs[16][132];
    __shared__ float red_d[128][17];
    __shared__ int   red_k[128][17];
    __shared__ int   s_bk[128];
    __shared__ float s_l[8];

    const float* A = (stage == 0) ? x : g_residual;
    const float* cn = g_cnorm + stage * KK_CB;

    int t  = threadIdx.x;
    int tx = t & 15, ty = t >> 4;
    int row0 = blockIdx.x * 128;

    float bestd[8];
    int   bestk[8];
    #pragma unroll
    for (int i = 0; i < 8; i++) { bestd[i] = 3.4e38f; bestk[i] = 0; }

    for (int nt = 0; nt < KK_CB / 128; ++nt) {
        unsigned long long acc[8][4];
        #pragma unroll
        for (int i = 0; i < 8; i++)
            #pragma unroll
            for (int j = 0; j < 4; j++) acc[i][j] = 0ULL;

        const float* Bbase = cb_stage + (size_t)nt * 128 * DD;

        for (int k0 = 0; k0 < DD; k0 += 16) {
            #pragma unroll
            for (int i = 0; i < 2; i++) {
                int idx = t + 256 * i;
                int r = idx >> 2, c = idx & 3;
                float4 va = *(const float4*)(A + (size_t)(row0 + r) * DD + k0 + 4 * c);
                As[4*c+0][r] = va.x; As[4*c+1][r] = va.y;
                As[4*c+2][r] = va.z; As[4*c+3][r] = va.w;
                float4 vb = *(const float4*)(Bbase + (size_t)r * DD + k0 + 4 * c);
                Bs[4*c+0][r] = vb.x; Bs[4*c+1][r] = vb.y;
                Bs[4*c+2][r] = vb.z; Bs[4*c+3][r] = vb.w;
            }
            __syncthreads();
            #pragma unroll
            for (int kk = 0; kk < 16; ++kk) {
                float a[8];
                *(float4*)(a)     = *(const float4*)&As[kk][ty * 8];
                *(float4*)(a + 4) = *(const float4*)&As[kk][ty * 8 + 4];
                unsigned long long b2[4];
                const unsigned long long* bp = (const unsigned long long*)&Bs[kk][tx * 8];
                b2[0] = bp[0]; b2[1] = bp[1]; b2[2] = bp[2]; b2[3] = bp[3];
                #pragma unroll
                for (int i = 0; i < 8; i++) {
                    unsigned long long a2 = pack2(a[i]);
                    fma2(acc[i][0], a2, b2[0]);
                    fma2(acc[i][1], a2, b2[1]);
                    fma2(acc[i][2], a2, b2[2]);
                    fma2(acc[i][3], a2, b2[3]);
                }
            }
            __syncthreads();
        }
        // fold this code tile into per-thread argmin (ascending col => ties keep first)
        #pragma unroll
        for (int i = 0; i < 8; i++) {
            #pragma unroll
            for (int j2 = 0; j2 < 4; j2++) {
                float2 v = unpack2(acc[i][j2]);
                int col = nt * 128 + tx * 8 + 2 * j2;
                float d0 = __ldg(cn + col)     - 2.0f * v.x;
                float d1 = __ldg(cn + col + 1) - 2.0f * v.y;
                if (d0 < bestd[i]) { bestd[i] = d0; bestk[i] = col; }
                if (d1 < bestd[i]) { bestd[i] = d1; bestk[i] = col + 1; }
            }
        }
    }
    #pragma unroll
    for (int i = 0; i < 8; i++) { red_d[ty*8+i][tx] = bestd[i]; red_k[ty*8+i][tx] = bestk[i]; }
    __syncthreads();
    if (t < 128) {
        float bd = red_d[t][0]; int bk = red_k[t][0];
        #pragma unroll
        for (int j = 1; j < 16; j++) {
            float d = red_d[t][j]; int k = red_k[t][j];
            if (d < bd || (d == bd && k < bk)) { bd = d; bk = k; }
        }
        g_idx[stage * NTOK + row0 + t] = bk;
        s_bk[t] = bk;
    }
    __syncthreads();

    // ---- fused update: residual -= q ; loss ; (stage 3) quant = x - residual_new ----
    const float4* src4 = (const float4*)A + (size_t)row0 * 128;
    float4*       res4 = (float4*)g_residual + (size_t)row0 * 128;
    const float4* cb4  = (const float4*)cb_stage;
    const float4* x4   = (const float4*)x + (size_t)row0 * 128;
    float4*       q4   = (float4*)quant + (size_t)row0 * 128;

    float lsum = 0.f;
    #pragma unroll 4
    for (int e = t; e < 128 * 128; e += 256) {
        int row = e >> 7, d4 = e & 127;
        int k = s_bk[row];
        float4 r = src4[e];
        float4 q = cb4[(size_t)k * 128 + d4];
        float nx = r.x - q.x, ny = r.y - q.y, nz = r.z - q.z, nw = r.w - q.w;
        lsum += nx * nx + ny * ny + nz * nz + nw * nw;
        res4[e] = make_float4(nx, ny, nz, nw);
        if (stage == QQ - 1) {
            float4 xv = x4[e];
            q4[e] = make_float4(xv.x - nx, xv.y - ny, xv.z - nz, xv.w - nw);
        }
    }
    #pragma unroll
    for (int o = 16; o > 0; o >>= 1) lsum += __shfl_down_sync(0xffffffffu, lsum, o);
    if ((t & 31) == 0) s_l[t >> 5] = lsum;
    __syncthreads();
    if (t == 0) {
        float s = 0.f;
        #pragma unroll
        for (int i = 0; i < 8; i++) s += s_l[i];
        atomicAdd(&g_loss, (double)s);
    }
}

// ---------------- conv1d (stride 2, SAME, pad_lo=1) + exact GELU via f32x2 ----------------
// GEMM: out[16384,512] = patches[16384, 5*512] x W[5*512, 512]
__global__ __launch_bounds__(256)
void conv_gelu_kernel(const float* __restrict__ quant,
                      const float* __restrict__ W,
                      float* __restrict__ y) {
    __shared__ __align__(16) float As[16][132];
    __shared__ __align__(16) float Bs[16][132];

    int t  = threadIdx.x;
    int tx = t & 15, ty = t >> 4;
    int mrow0 = blockIdx.x * 128;
    int ncol0 = blockIdx.y * 128;

    unsigned long long acc[8][4];
    #pragma unroll
    for (int i = 0; i < 8; i++)
        #pragma unroll
        for (int j = 0; j < 4; j++) acc[i][j] = 0ULL;

    for (int kk = 0; kk < KER; ++kk) {
        const float* Wk = W + (size_t)kk * DD * DD;
        for (int c0 = 0; c0 < DD; c0 += 16) {
            #pragma unroll
            for (int i = 0; i < 2; i++) {
                int idx = t + 256 * i;
                // A tile: 128 out-rows x 16 channels
                int r = idx >> 2, c = idx & 3;
                int row = mrow0 + r;
                int b   = row >> 11;          // / TOUT
                int to  = row & (TOUT - 1);
                int tin = 2 * to + kk - 1;    // SAME: pad_lo = 1
                float4 va = make_float4(0.f, 0.f, 0.f, 0.f);
                if ((unsigned)tin < (unsigned)TT)
                    va = *(const float4*)(quant + ((size_t)b * TT + tin) * DD + c0 + 4 * c);
                As[4*c+0][r] = va.x; As[4*c+1][r] = va.y;
                As[4*c+2][r] = va.z; As[4*c+3][r] = va.w;
                // B tile: 16 in-channels x 128 out-channels
                int ci = idx >> 5, cq = idx & 31;
                float4 vb = *(const float4*)(Wk + (size_t)(c0 + ci) * DD + ncol0 + cq * 4);
                *(float4*)&Bs[ci][cq * 4] = vb;
            }
            __syncthreads();
            #pragma unroll
            for (int kki = 0; kki < 16; ++kki) {
                float a[8];
                *(float4*)(a)     = *(const float4*)&As[kki][ty * 8];
                *(float4*)(a + 4) = *(const float4*)&As[kki][ty * 8 + 4];
                unsigned long long b2[4];
                const unsigned long long* bp = (const unsigned long long*)&Bs[kki][tx * 8];
                b2[0] = bp[0]; b2[1] = bp[1]; b2[2] = bp[2]; b2[3] = bp[3];
                #pragma unroll
                for (int i = 0; i < 8; i++) {
                    unsigned long long a2 = pack2(a[i]);
                    fma2(acc[i][0], a2, b2[0]);
                    fma2(acc[i][1], a2, b2[1]);
                    fma2(acc[i][2], a2, b2[2]);
                    fma2(acc[i][3], a2, b2[3]);
                }
            }
            __syncthreads();
        }
    }
    #pragma unroll
    for (int i = 0; i < 8; i++) {
        int row = mrow0 + ty * 8 + i;
        #pragma unroll
        for (int j2 = 0; j2 < 4; j2++) {
            float2 v = unpack2(acc[i][j2]);
            int co = ncol0 + tx * 8 + 2 * j2;
            float g0 = 0.5f * v.x * (1.0f + erff(v.x * 0.70710678118654752f));
            float g1 = 0.5f * v.y * (1.0f + erff(v.y * 0.70710678118654752f));
            y[(size_t)row * DD + co]     = g0;
            y[(size_t)row * DD + co + 1] = g1;
        }
    }
}

// ---------------- indices (as float) + loss ----------------
__global__ void finalize_kernel(float* __restrict__ out) {
    int i = blockIdx.x * blockDim.x + threadIdx.x;
    if (i < IDX_SZ) out[Y_SZ + QO_SZ + i] = (float)g_idx[i];
    if (i == 0)     out[LOSS_OFF] = (float)(0.25 * g_loss / (double)NELEM);
}

// ---------------- launch ----------------
extern "C" void kernel_launch(void* const* d_in, const int* in_sizes, int n_in,
                              void* d_out, int out_size) {
    const float* x  = (const float*)d_in[0];
    const float* cb = (const float*)d_in[1];
    const float* w  = (const float*)d_in[2];
    float* out   = (float*)d_out;
    float* y     = out;
    float* quant = out + Y_SZ;

    cnorm_kernel<<<(QQ * KK_CB * 32 + 255) / 256, 256>>>(cb);
    for (int s = 0; s < QQ; ++s)
        vq_stage_kernel<<<NTOK / 128, 256>>>(x, cb + (size_t)s * KK_CB * DD, quant, s);
    conv_gelu_kernel<<<dim3(BB * TOUT / 128, DD / 128), 256>>>(quant, w, y);
    finalize_kernel<<<(IDX_SZ + 255) / 256, 256>>>(out);
}